// round 5
// baseline (speedup 1.0000x reference)
#include <cuda_runtime.h>
#include <math.h>
#include <stdint.h>

#define TT     128
#define BB     64
#define IDIMq  256
#define CDIMq  512
#define RRq    4
#define NNq    128
#define WWq    64
#define IFACEq 471
#define EPSq   1e-6f
#define DELTAq 5e-6f
#define CATW   768
#define NBLK   128

// ---------------- static device scratch ----------------
__device__ float g_G   [(size_t)TT * BB * 4 * CDIMq];
__device__ float g_h0  [(size_t)TT * BB * CDIMq];
__device__ float g_h1  [(size_t)TT * BB * CDIMq];
__device__ float g_cat [(size_t)TT * BB * CATW];
__device__ float g_xi  [(size_t)TT * BB * IFACEq];
__device__ unsigned g_bar_cnt = 0;
__device__ unsigned g_bar_gen = 0;

__device__ __forceinline__ float sigm(float x)  { return 1.f / (1.f + expf(-x)); }
__device__ __forceinline__ float splus(float x) { return fmaxf(x, 0.f) + log1pf(expf(-fabsf(x))); }
__device__ __forceinline__ float warp_sum(float v) {
#pragma unroll
    for (int o = 16; o; o >>= 1) v += __shfl_xor_sync(0xffffffffu, v, o);
    return v;
}
__device__ __forceinline__ float warp_max(float v) {
#pragma unroll
    for (int o = 16; o; o >>= 1) v = fmaxf(v, __shfl_xor_sync(0xffffffffu, v, o));
    return v;
}

__device__ __forceinline__ void cp16(uint32_t dst, const void* src) {
    asm volatile("cp.async.cg.shared.global [%0], [%1], 16;" :: "r"(dst), "l"(src));
}
__device__ __forceinline__ void cp_commit_wait() {
    asm volatile("cp.async.commit_group;");
    asm volatile("cp.async.wait_group 0;");
}

// ---------------- two-phase grid barrier (all NBLK blocks co-resident) ----------------
__device__ __forceinline__ void grid_sync() {
    __syncthreads();
    if (threadIdx.x == 0) {
        __threadfence();
        unsigned gen = *(volatile unsigned*)&g_bar_gen;
        unsigned arr = atomicAdd(&g_bar_cnt, 1);
        if (arr == NBLK - 1) {
            atomicExch(&g_bar_cnt, 0);
            __threadfence();
            atomicExch(&g_bar_gen, gen + 1);
        } else {
            while (*(volatile unsigned*)&g_bar_gen == gen) { }
        }
        __threadfence();
    }
    __syncthreads();
}

// ---------------- SGEMM: C[M,N] = A[M,K] @ B[N,K]^T + bias1 (+bias2) ----------------
__global__ void __launch_bounds__(256) sgemm_bt(
    const float* __restrict__ A, int lda,
    const float* __restrict__ B, int ldb,
    float* __restrict__ C, int ldc,
    const float* __restrict__ bias1, const float* __restrict__ bias2,
    int N, int K)
{
    __shared__ float As[8][128];
    __shared__ float Bs[8][128];
    const int m0 = blockIdx.y * 128, n0 = blockIdx.x * 128;
    const int tid = threadIdx.x;
    const int lrow = tid >> 1;
    const int lk = (tid & 1) * 4;
    const int tx = tid & 15, ty = tid >> 4;

    float acc[8][8];
#pragma unroll
    for (int i = 0; i < 8; i++)
#pragma unroll
        for (int j = 0; j < 8; j++) acc[i][j] = 0.f;

    for (int k0 = 0; k0 < K; k0 += 8) {
        float4 av = *(const float4*)(A + (size_t)(m0 + lrow) * lda + k0 + lk);
        As[lk + 0][lrow] = av.x; As[lk + 1][lrow] = av.y;
        As[lk + 2][lrow] = av.z; As[lk + 3][lrow] = av.w;
        int nr = n0 + lrow;
        float4 bv = make_float4(0.f, 0.f, 0.f, 0.f);
        if (nr < N) bv = *(const float4*)(B + (size_t)nr * ldb + k0 + lk);
        Bs[lk + 0][lrow] = bv.x; Bs[lk + 1][lrow] = bv.y;
        Bs[lk + 2][lrow] = bv.z; Bs[lk + 3][lrow] = bv.w;
        __syncthreads();
#pragma unroll
        for (int k = 0; k < 8; k++) {
            float4 a0 = *(float4*)&As[k][ty * 8 + 0];
            float4 a1 = *(float4*)&As[k][ty * 8 + 4];
            float4 b0 = *(float4*)&Bs[k][tx * 8 + 0];
            float4 b1 = *(float4*)&Bs[k][tx * 8 + 4];
            float ar[8] = {a0.x, a0.y, a0.z, a0.w, a1.x, a1.y, a1.z, a1.w};
            float br[8] = {b0.x, b0.y, b0.z, b0.w, b1.x, b1.y, b1.z, b1.w};
#pragma unroll
            for (int i = 0; i < 8; i++)
#pragma unroll
                for (int j = 0; j < 8; j++) acc[i][j] += ar[i] * br[j];
        }
        __syncthreads();
    }
#pragma unroll
    for (int i = 0; i < 8; i++) {
        int m = m0 + ty * 8 + i;
#pragma unroll
        for (int j = 0; j < 8; j++) {
            int n = n0 + tx * 8 + j;
            if (n < N) {
                float v = acc[i][j] + bias1[n];
                if (bias2) v += bias2[n];
                C[(size_t)m * ldc + n] = v;
            }
        }
    }
}

// ---------------- persistent LSTM layer: all 128 steps, one kernel ----------------
// 128 blocks x 512 threads (16 warps, 4/SMSP); block owns 4 h-features (16 gate-rows
// of Whh, smem-resident). Per step: cp.async-stage h(t-1), 8x8 register-tile matvec
// with 32-way k-split (16 warps x 2 subs), shfl + two-phase smem reduce, gates
// (c in registers, tid<256), grid barrier.
#define WPITCH 520
#define HPITCH 520
#define WSM_SZ 8320
#define HSM_SZ 33360
#define RSM_SZ 8192
#define PSM_FLOATS (WSM_SZ + HSM_SZ + RSM_SZ)

__global__ void __launch_bounds__(512, 1) lstm_persist(
    const float* __restrict__ Gpre_all,  // [TT][BB][2048] (ih + both biases)
    const float* __restrict__ Whh,       // [2048][512]
    float*       hhist,                  // [TT][BB][512]
    float*       clipout)                // null or g_cat base
{
    extern __shared__ float sm[];
    float* Wsm = sm;
    float* Hsm = sm + WSM_SZ;
    float* Rsm = sm + WSM_SZ + HSM_SZ;

    const int tid = threadIdx.x, bid = blockIdx.x;
    const int warp = tid >> 5, lane = tid & 31;
    const int tile = lane & 15, sub = lane >> 4;
    const int r0 = (tile >> 3) * 8, b0 = (tile & 7) * 8;
    const int kb = warp * 32 + sub * 16;      // 16 k per (warp, sub)
    const int wbase = r0 * WPITCH + (r0 >> 3) * 8;
    const int hbase = b0 * HPITCH + (b0 >> 3) * 12;
    const uint32_t hsm_u32 = (uint32_t)__cvta_generic_to_shared(Hsm);

    // stage this block's 16 gate-rows of Whh once
    for (int idx = tid; idx < 16 * 128; idx += 512) {
        int r = idx >> 7, kq = idx & 127;
        int grow = (r >> 2) * 512 + bid * 4 + (r & 3);
        *(float4*)&Wsm[r * WPITCH + (r >> 3) * 8 + kq * 4] =
            *(const float4*)&Whh[(size_t)grow * 512 + kq * 4];
    }

    const int jl = tid >> 6;        // valid for tid<256: local feature 0..3
    const int bb = tid & 63;        // batch
    const int jf = bid * 4 + jl;    // global feature
    float c = 0.f;

    for (int t = 0; t < TT; t++) {
        // ---- stage h(t-1) into skewed smem ----
        if (t == 0) {
            for (int idx = tid; idx < 64 * 128; idx += 512) {
                int b = idx >> 7, kq = idx & 127;
                *(float4*)&Hsm[b * HPITCH + (b >> 3) * 12 + kq * 4] = make_float4(0.f, 0.f, 0.f, 0.f);
            }
        } else {
            const float4* hsrc = (const float4*)(hhist + (size_t)(t - 1) * BB * 512);
#pragma unroll
            for (int ii = 0; ii < 16; ii++) {
                int idx = tid + ii * 512;
                int b = idx >> 7, kq = idx & 127;
                cp16(hsm_u32 + (uint32_t)(b * HPITCH + (b >> 3) * 12 + kq * 4) * 4u,
                     hsrc + b * 128 + kq);
            }
            cp_commit_wait();
        }
        __syncthreads();

        // ---- 8x8 register-tile matvec over this thread's 16-wide k-chunk ----
        float acc[8][8];
#pragma unroll
        for (int i = 0; i < 8; i++)
#pragma unroll
            for (int j = 0; j < 8; j++) acc[i][j] = 0.f;

        const float* wp0 = Wsm + wbase;
        const float* hp0 = Hsm + hbase;
#pragma unroll
        for (int j8 = 0; j8 < 4; j8++) {
            const int k = kb + j8 * 4;
            float4 hv[8];
#pragma unroll
            for (int j = 0; j < 8; j++) hv[j] = *(const float4*)(hp0 + j * HPITCH + k);
#pragma unroll
            for (int i = 0; i < 8; i++) {
                float4 wv = *(const float4*)(wp0 + i * WPITCH + k);
#pragma unroll
                for (int j = 0; j < 8; j++)
                    acc[i][j] += wv.x * hv[j].x + wv.y * hv[j].y
                               + wv.z * hv[j].z + wv.w * hv[j].w;
            }
        }

        // ---- combine sub halves in-warp ----
#pragma unroll
        for (int i = 0; i < 8; i++)
#pragma unroll
            for (int j = 0; j < 8; j++)
                acc[i][j] += __shfl_xor_sync(0xffffffffu, acc[i][j], 16);

        // ---- two-phase smem reduce: warps 8-15 write, warps 0-7 accumulate ----
        if (warp >= 8 && lane < 16) {
#pragma unroll
            for (int i = 0; i < 8; i++) {
                float* dst = &Rsm[(warp - 8) * 1024 + (r0 + i) * 64 + b0];
                *(float4*)dst       = make_float4(acc[i][0], acc[i][1], acc[i][2], acc[i][3]);
                *(float4*)(dst + 4) = make_float4(acc[i][4], acc[i][5], acc[i][6], acc[i][7]);
            }
        }
        __syncthreads();
        if (warp < 8 && lane < 16) {
#pragma unroll
            for (int i = 0; i < 8; i++) {
                float* dst = &Rsm[warp * 1024 + (r0 + i) * 64 + b0];
                float4 p0 = *(float4*)dst, p1 = *(float4*)(dst + 4);
                p0.x += acc[i][0]; p0.y += acc[i][1]; p0.z += acc[i][2]; p0.w += acc[i][3];
                p1.x += acc[i][4]; p1.y += acc[i][5]; p1.z += acc[i][6]; p1.w += acc[i][7];
                *(float4*)dst = p0; *(float4*)(dst + 4) = p1;
            }
        }
        __syncthreads();

        // ---- gate math (tid < 256): sum 8 partials, add Gpre, update c,h ----
        if (tid < 256) {
            float g4[4];
#pragma unroll
            for (int g = 0; g < 4; g++) {
                int r = g * 4 + jl;
                float s = 0.f;
#pragma unroll
                for (int p = 0; p < 8; p++) s += Rsm[p * 1024 + r * 64 + bb];
                g4[g] = s;
            }
            const float* gp = Gpre_all + ((size_t)t * BB + bb) * 2048 + jf;
            float gi = g4[0] + gp[0];
            float gf = g4[1] + gp[512];
            float gg = g4[2] + gp[1024];
            float go = g4[3] + gp[1536];
            c = sigm(gf) * c + sigm(gi) * tanhf(gg);
            float h = sigm(go) * tanhf(c);
            hhist[((size_t)t * BB + bb) * 512 + jf] = h;
            if (clipout) clipout[((size_t)t * BB + bb) * CATW + jf] = fminf(fmaxf(h, -20.f), 20.f);
        }

        if (t + 1 < TT) grid_sync();
    }
}

// ---------------- DNC memory module (unchanged) ----------------
struct MemSmem {
    float mem[NNq][WWq + 1];
    float link[NNq][NNq + 1];
    float prec[NNq], usage[NNq], ww[NNq];
    float rw[RRq][NNq], rw2[RRq][NNq], fwd[RRq][NNq], bwd[RRq][NNq], rc[RRq][NNq];
    float wc[NNq], u[NNq], su[NNq], pe[NNq], norms[NNq];
    int   rank[NNq];
    float rkeys[RRq][WWq];
    float wkey[WWq], wvec[WWq], erase[WWq];
    float rstr[RRq], fg[RRq], rknorm[RRq];
    float modes[RRq][3];
    float scal[8];
};
#define S_WSTR 0
#define S_AG   1
#define S_WG   2
#define S_KN   3
#define S_SWW  4

__global__ void __launch_bounds__(256) memory_kernel(
    const float* __restrict__ xi_all, float* __restrict__ cat)
{
    extern __shared__ __align__(16) char smraw[];
    MemSmem* s = (MemSmem*)smraw;
    const int b = blockIdx.x, tid = threadIdx.x;

    for (int i = tid; i < (int)(sizeof(MemSmem) / 4); i += 256) ((float*)smraw)[i] = 0.f;
    __syncthreads();

    for (int t = 0; t < TT; t++) {
        const float* xi = xi_all + ((size_t)t * BB + b) * IFACEq;

        { int r = tid >> 6, w = tid & 63; s->rkeys[r][w] = tanhf(xi[tid]); }
        if (tid < 64) {
            s->wkey[tid]  = tanhf(xi[260 + tid]);
            s->erase[tid] = sigm (xi[325 + tid]);
            s->wvec[tid]  = tanhf(xi[389 + tid]);
        } else if (tid < 68) s->rstr[tid - 64] = splus(xi[256 + tid - 64]);
        else if (tid < 72)   s->fg[tid - 68]   = sigm (xi[453 + tid - 68]);
        else if (tid == 72)  s->scal[S_WSTR]   = splus(xi[324]);
        else if (tid == 73)  s->scal[S_AG]     = sigm (xi[457]);
        else if (tid == 74)  s->scal[S_WG]     = sigm (xi[458]);
        else if (tid >= 80 && tid < 84) {
            int r = tid - 80;
            float x0 = xi[459 + 3*r], x1 = xi[460 + 3*r], x2 = xi[461 + 3*r];
            float m = fmaxf(x0, fmaxf(x1, x2));
            float e0 = expf(x0 - m), e1 = expf(x1 - m), e2 = expf(x2 - m);
            float inv = 1.f / (e0 + e1 + e2);
            s->modes[r][0] = e0*inv; s->modes[r][1] = e1*inv; s->modes[r][2] = e2*inv;
        }
        __syncthreads();

        if (tid < 128) {
            float us = s->usage[tid] + (1.f - s->usage[tid]) * s->ww[tid];
            float ret = 1.f;
#pragma unroll
            for (int r = 0; r < RRq; r++) ret *= (1.f - s->fg[r] * s->rw[r][tid]);
            s->usage[tid] = us * ret;
            float ss = 0.f;
#pragma unroll 8
            for (int w = 0; w < WWq; w++) { float v = s->mem[tid][w]; ss += v * v; }
            s->norms[tid] = sqrtf(ss);
        } else if (tid < 160) {
            int l = tid - 128;
            float p = s->wkey[l]*s->wkey[l] + s->wkey[l+32]*s->wkey[l+32];
            p = warp_sum(p);
            if (l == 0) s->scal[S_KN] = sqrtf(p);
        } else if (tid < 164) {
            int r = tid - 160; float ss = 0.f;
            for (int w = 0; w < WWq; w++) ss += s->rkeys[r][w]*s->rkeys[r][w];
            s->rknorm[r] = sqrtf(ss);
        }
        __syncthreads();

        if (tid < 128) {
            float d = 0.f;
#pragma unroll 8
            for (int w = 0; w < WWq; w++) d += s->wkey[w] * s->mem[tid][w];
            s->wc[tid] = d / ((s->norms[tid] + EPSq) * (s->scal[S_KN] + EPSq)) * s->scal[S_WSTR];
        }
        __syncthreads();
        if (tid < 32) {
            float v0 = s->wc[tid], v1 = s->wc[tid+32], v2 = s->wc[tid+64], v3 = s->wc[tid+96];
            float mx = warp_max(fmaxf(fmaxf(v0, v1), fmaxf(v2, v3)));
            v0 = expf(v0-mx); v1 = expf(v1-mx); v2 = expf(v2-mx); v3 = expf(v3-mx);
            float inv = 1.f / warp_sum(v0 + v1 + v2 + v3);
            s->wc[tid] = v0*inv; s->wc[tid+32] = v1*inv; s->wc[tid+64] = v2*inv; s->wc[tid+96] = v3*inv;
        }
        __syncthreads();

        if (tid < 128) s->u[tid] = DELTAq + (1.f - DELTAq) * s->usage[tid];
        __syncthreads();
        if (tid < 128) {
            float ui = s->u[tid]; int rk = 0;
            for (int j = 0; j < 128; j++) {
                float uj = s->u[j];
                rk += (uj < ui) || (uj == ui && j < tid);
            }
            s->rank[tid] = rk;
            s->su[rk] = ui;
        }
        __syncthreads();
        if (tid < 128) s->pe[tid] = s->su[tid];
        __syncthreads();
        for (int d = 1; d < 128; d <<= 1) {
            float v = 1.f;
            if (tid < 128 && tid >= d) v = s->pe[tid - d];
            __syncthreads();
            if (tid < 128 && tid >= d) s->pe[tid] *= v;
            __syncthreads();
        }
        if (tid < 128) {
            int rk = s->rank[tid];
            float excl = rk ? s->pe[rk - 1] : 1.f;
            float alloc = (1.f - s->u[tid]) * excl;
            float ag = s->scal[S_AG], wg = s->scal[S_WG];
            s->ww[tid] = wg * (ag * alloc + (1.f - ag) * s->wc[tid]);
        }
        __syncthreads();
        if (tid < 32) {
            float v = s->ww[tid] + s->ww[tid+32] + s->ww[tid+64] + s->ww[tid+96];
            v = warp_sum(v);
            if (tid == 0) s->scal[S_SWW] = v;
        }
        __syncthreads();

        {
            int w = tid & 63, ng = tid >> 6;
            for (int i = 0; i < 32; i++) {
                int n = ng * 32 + i;
                float wwn = s->ww[n];
                s->mem[n][w] = s->mem[n][w] * (1.f - wwn * s->erase[w]) + wwn * s->wvec[w];
            }
        }
        {
            int i = tid >> 1, j0 = (tid & 1) * 64;
            float wwi = s->ww[i];
            for (int jj = 0; jj < 64; jj++) {
                int j = j0 + jj;
                float l = (1.f - wwi - s->ww[j]) * s->link[i][j] + wwi * s->prec[j];
                s->link[i][j] = (i == j) ? 0.f : l;
            }
        }
        __syncthreads();
        if (tid < 128) {
            s->prec[tid] = (1.f - s->scal[S_SWW]) * s->prec[tid] + s->ww[tid];
            float ss = 0.f;
#pragma unroll 8
            for (int w = 0; w < WWq; w++) { float v = s->mem[tid][w]; ss += v * v; }
            s->norms[tid] = sqrtf(ss);
        }
        __syncthreads();

        for (int p = tid; p < 512; p += 256) {
            int r = p >> 7, n = p & 127;
            float d = 0.f;
#pragma unroll 8
            for (int w = 0; w < WWq; w++) d += s->rkeys[r][w] * s->mem[n][w];
            s->rc[r][n] = d / ((s->norms[n] + EPSq) * (s->rknorm[r] + EPSq)) * s->rstr[r];
        }
        __syncthreads();
        if (tid < 128) {
            int r = tid >> 5, l = tid & 31;
            float v0 = s->rc[r][l], v1 = s->rc[r][l+32], v2 = s->rc[r][l+64], v3 = s->rc[r][l+96];
            float mx = warp_max(fmaxf(fmaxf(v0, v1), fmaxf(v2, v3)));
            v0 = expf(v0-mx); v1 = expf(v1-mx); v2 = expf(v2-mx); v3 = expf(v3-mx);
            float inv = 1.f / warp_sum(v0 + v1 + v2 + v3);
            s->rc[r][l] = v0*inv; s->rc[r][l+32] = v1*inv; s->rc[r][l+64] = v2*inv; s->rc[r][l+96] = v3*inv;
        }
        __syncthreads();

        for (int p = tid; p < 512; p += 256) {
            int r = p >> 7, n = p & 127;
            float f = 0.f, bw = 0.f;
#pragma unroll 4
            for (int m = 0; m < 128; m++) {
                float rv = s->rw[r][m];
                f  += rv * s->link[n][m];
                bw += rv * s->link[m][n];
            }
            s->fwd[r][n] = f; s->bwd[r][n] = bw;
        }
        __syncthreads();
        for (int p = tid; p < 512; p += 256) {
            int r = p >> 7, n = p & 127;
            s->rw2[r][n] = s->modes[r][0]*s->bwd[r][n] + s->modes[r][1]*s->rc[r][n] + s->modes[r][2]*s->fwd[r][n];
        }
        __syncthreads();
        for (int p = tid; p < 512; p += 256) { int r = p >> 7, n = p & 127; s->rw[r][n] = s->rw2[r][n]; }
        __syncthreads();

        {
            int r = tid >> 6, w = tid & 63;
            float acc = 0.f;
#pragma unroll 4
            for (int n = 0; n < 128; n++) acc += s->rw[r][n] * s->mem[n][w];
            cat[((size_t)t * BB + b) * CATW + 512 + tid] = acc;
        }
        __syncthreads();
    }
}

__global__ void gather_hid(float* __restrict__ out, const int* __restrict__ lens) {
    int b = blockIdx.x, i = threadIdx.x;
    int t = lens[b] - 1;
    out[(size_t)TT * BB * IDIMq + (size_t)b * IDIMq + i] = out[((size_t)t * BB + b) * IDIMq + i];
}

extern "C" void kernel_launch(void* const* d_in, const int* in_sizes, int n_in,
                              void* d_out, int out_size) {
    const float* embs = (const float*)d_in[0];
    const int*   lens = (const int*)  d_in[1];
    const float* Wih0 = (const float*)d_in[2];
    const float* Whh0 = (const float*)d_in[3];
    const float* bih0 = (const float*)d_in[4];
    const float* bhh0 = (const float*)d_in[5];
    const float* Wih1 = (const float*)d_in[6];
    const float* Whh1 = (const float*)d_in[7];
    const float* bih1 = (const float*)d_in[8];
    const float* bhh1 = (const float*)d_in[9];
    const float* Wxi  = (const float*)d_in[10];
    const float* bxi  = (const float*)d_in[11];
    const float* Wout = (const float*)d_in[12];
    const float* bout = (const float*)d_in[13];
    float* out = (float*)d_out;

    float *G, *h0, *h1, *cat, *xi;
    cudaGetSymbolAddress((void**)&G,   g_G);
    cudaGetSymbolAddress((void**)&h0,  g_h0);
    cudaGetSymbolAddress((void**)&h1,  g_h1);
    cudaGetSymbolAddress((void**)&cat, g_cat);
    cudaGetSymbolAddress((void**)&xi,  g_xi);

    cudaFuncSetAttribute(memory_kernel, cudaFuncAttributeMaxDynamicSharedMemorySize,
                         (int)sizeof(MemSmem));
    cudaFuncSetAttribute(lstm_persist, cudaFuncAttributeMaxDynamicSharedMemorySize,
                         PSM_FLOATS * 4);

    // Gih0 = embs @ Wih0[:, :256]^T + bih0 + bhh0   (zeros_read contributes nothing)
    sgemm_bt<<<dim3(16, 64), 256>>>(embs, IDIMq, Wih0, CDIMq, G, 2048, bih0, bhh0, 2048, IDIMq);

    // layer 0: all 128 steps, one persistent kernel
    lstm_persist<<<NBLK, 512, PSM_FLOATS * 4>>>(G, Whh0, h0, nullptr);

    // Gih1 = h0 @ Wih1^T + bih1 + bhh1
    sgemm_bt<<<dim3(16, 64), 256>>>(h0, CDIMq, Wih1, CDIMq, G, 2048, bih1, bhh1, 2048, CDIMq);

    // layer 1: all 128 steps, one persistent kernel (also writes clip(h1) into cat)
    lstm_persist<<<NBLK, 512, PSM_FLOATS * 4>>>(G, Whh1, h1, cat);

    // xi = clip(h1) @ Wxi^T + bxi
    sgemm_bt<<<dim3(4, 64), 256>>>(cat, CATW, Wxi, CDIMq, xi, IFACEq, bxi, nullptr, IFACEq, CDIMq);

    memory_kernel<<<64, 256, sizeof(MemSmem)>>>(xi, cat);

    // y = cat @ Wout^T + bout
    sgemm_bt<<<dim3(2, 64), 256>>>(cat, CATW, Wout, CATW, out, IDIMq, bout, nullptr, IDIMq, CATW);

    gather_hid<<<64, 256>>>(out, lens);
}